// round 8
// baseline (speedup 1.0000x reference)
#include <cuda_runtime.h>
#include <cuda_fp16.h>
#include <stdint.h>
#include <math.h>

#define D_ 128
#define K_ 8
#define XS 136                 // fp16 X tile stride (halves)
#define NTT 18                 // n-tiles in bfrag table: 16 data + 2 stats

// ---- main-kernel dynamic smem layout (bytes) ----
#define SM_X1    0             // 128 x XS halves = 34816
#define SM_X2    34816         // -> 69632
#define SM_CB    69632         // float[8][128] raw codebook -> 73728
#define SM_BG2   73728         // float2[128] {bias, gamma^2} -> 74752
#define SM_STAT  74752         // float2[128][9] padded stats -> 83968
#define SM_Q     83968         // float[128][5] padded quad partials -> 86528
#define SM_IDX   86528         // int[128] -> 87040
#define SMEM_TOTAL 87040

// W + stats pre-split fp16 hi/lo in m16n8k16 B-fragment order:
// g_bfrag[(ks*NTT + gnt)*32 + lane] = {B1hi_r0, B1hi_r1, B1lo_r0, B1lo_r1}
__device__ uint4 g_bfrag[8 * NTT * 32];
__device__ float2 g_bg2[128];     // {bias[c], gamma[c]^2}
// consts: [0..10]=C[j]=Sum bias*v_j, [11]=Sum g^2, [12]=Sum g*bt, [13]=Sum bt^2,
//         [14+k]=e[k]=Sum g*cbn[k], [22+k]=d[k]=Sum bt*cbn[k]
__device__ float g_sc2[30];

__device__ __forceinline__ uint32_t smem_u32(const void* p) {
    uint32_t a;
    asm("{ .reg .u64 t; cvta.to.shared.u64 t, %1; cvt.u32.u64 %0, t; }" : "=r"(a) : "l"(p));
    return a;
}
__device__ __forceinline__ void ldsm_x4(uint32_t& r0, uint32_t& r1, uint32_t& r2, uint32_t& r3,
                                        uint32_t addr) {
    asm volatile("ldmatrix.sync.aligned.m8n8.x4.shared.b16 {%0,%1,%2,%3}, [%4];"
                 : "=r"(r0), "=r"(r1), "=r"(r2), "=r"(r3) : "r"(addr));
}
__device__ __forceinline__ void mma16816(float* c, const uint32_t* a, uint32_t b0, uint32_t b1) {
    asm volatile(
        "mma.sync.aligned.m16n8k16.row.col.f32.f16.f16.f32 "
        "{%0,%1,%2,%3}, {%4,%5,%6,%7}, {%8,%9}, {%0,%1,%2,%3};"
        : "+f"(c[0]), "+f"(c[1]), "+f"(c[2]), "+f"(c[3])
        : "r"(a[0]), "r"(a[1]), "r"(a[2]), "r"(a[3]), "r"(b0), "r"(b1));
}
__device__ __forceinline__ void split2(float x, float y, uint32_t& hi, uint32_t& lo) {
    __half hx = __float2half_rn(x), hy = __float2half_rn(y);
    __half lx = __float2half_rn(x - __half2float(hx));
    __half ly = __float2half_rn(y - __half2float(hy));
    __half2 h2 = __halves2half2(hx, hy), l2 = __halves2half2(lx, ly);
    hi = *(uint32_t*)&h2; lo = *(uint32_t*)&l2;
}
__device__ __forceinline__ float red4(float v) {
    v += __shfl_xor_sync(0xffffffffu, v, 1);
    v += __shfl_xor_sync(0xffffffffu, v, 2);
    return v;
}

// ---- prep ----
__global__ void l1q_prep(const float* __restrict__ W, const float* __restrict__ cb,
                         const float* __restrict__ bias, const float* __restrict__ gamma,
                         const float* __restrict__ beta) {
    const int tid = threadIdx.x;
    if (blockIdx.x < 16) {
        const int t = blockIdx.x * 256 + tid;           // 0..4095
        const int lane = t & 31;
        const int gnt = (t >> 5) & 15;
        const int ks = t >> 9;
        const int n = gnt * 8 + (lane >> 2);
        const int k0 = ks * 16 + ((lane & 3) << 1);
        const float* wr = W + n * 128;
        uint4 f;
        split2(wr[k0],     wr[k0 + 1], f.x, f.z);
        split2(wr[k0 + 8], wr[k0 + 9], f.y, f.w);
        g_bfrag[(ks * NTT + gnt) * 32 + lane] = f;
    } else {
        __shared__ float inv[K_];
        __shared__ float cbn[K_ * D_];
        __shared__ float V[11][128];
        __shared__ float red[30][128];
        if (tid < K_) {
            float s = 0.f;
            #pragma unroll 8
            for (int j = 0; j < D_; ++j) { float v = cb[tid * D_ + j]; s += v * v; }
            inv[tid] = 1.f / fmaxf(sqrtf(s), 1e-12f);
        }
        __syncthreads();
        for (int i = tid; i < K_ * D_; i += 256) cbn[i] = cb[i] * inv[i >> 7];
        __syncthreads();
        // V[j][k] = sum_c v_j[c] * W[c][k];  v0=1, v1=g^2, v2=g*bt, v_{3+kk}=g*cbn[kk]
        if (tid < 128) {
            const int k = tid;
            float a0 = 0, a1 = 0, a2 = 0, aS[8] = {0,0,0,0,0,0,0,0};
            for (int c = 0; c < 128; ++c) {
                float w = W[c * 128 + k];
                float g = gamma[c], bt = beta[c];
                a0 += w;
                a1 = fmaf(w, g * g, a1);
                a2 = fmaf(w, g * bt, a2);
                float wg = w * g;
                #pragma unroll
                for (int kk = 0; kk < 8; ++kk) aS[kk] = fmaf(wg, cbn[kk * 128 + c], aS[kk]);
            }
            V[0][k] = a0; V[1][k] = a1; V[2][k] = a2;
            #pragma unroll
            for (int kk = 0; kk < 8; ++kk) V[3 + kk][k] = aS[kk];
            g_bg2[k] = make_float2(bias[k], gamma[k] * gamma[k]);
        }
        __syncthreads();
        // stats fragments: gnt 16 (j 0-7), gnt 17 (j 8-15; j>=11 zero)
        for (int e = tid; e < 512; e += 256) {
            const int lane = e & 31;
            const int g16 = (e >> 5) & 1;
            const int ks = e >> 6;
            const int j = g16 * 8 + (lane >> 2);
            const int k0 = ks * 16 + ((lane & 3) << 1);
            float a = 0, b = 0, c2 = 0, d2 = 0;
            if (j < 11) { a = V[j][k0]; b = V[j][k0 + 1]; c2 = V[j][k0 + 8]; d2 = V[j][k0 + 9]; }
            uint4 f;
            split2(a, b, f.x, f.z);
            split2(c2, d2, f.y, f.w);
            g_bfrag[(ks * NTT + 16 + g16) * 32 + lane] = f;
        }
        // scalar consts
        if (tid < 128) {
            const int c = tid;
            float g = gamma[c], bt = beta[c], bs = bias[c];
            red[0][c] = bs;                 // C0: bias * 1
            red[1][c] = bs * g * g;         // C1
            red[2][c] = bs * g * bt;        // C2
            #pragma unroll
            for (int kk = 0; kk < 8; ++kk) red[3 + kk][c] = bs * g * cbn[kk * 128 + c];
            red[11][c] = g * g;
            red[12][c] = g * bt;
            red[13][c] = bt * bt;
            #pragma unroll
            for (int kk = 0; kk < 8; ++kk) {
                red[14 + kk][c] = g * cbn[kk * 128 + c];
                red[22 + kk][c] = bt * cbn[kk * 128 + c];
            }
        }
        __syncthreads();
        if (tid < 30) {
            float s = 0.f;
            for (int c = 0; c < 128; ++c) s += red[tid][c];
            g_sc2[tid] = s;
        }
    }
}

__global__ __launch_bounds__(256, 2) void l1q_mma(
    const float* __restrict__ X, const float* __restrict__ cb,
    float* __restrict__ out, int B, long out_size)
{
    extern __shared__ char smem[];
    const int tid = threadIdx.x;
    const int wid = tid >> 5;
    const int lane = tid & 31;
    const int row0 = blockIdx.x * 128;

    __half* sX1 = (__half*)(smem + SM_X1);
    __half* sX2 = (__half*)(smem + SM_X2);
    float*  s_cb = (float*)(smem + SM_CB);
    float2* s_bg2 = (float2*)(smem + SM_BG2);
    float2* s_stat = (float2*)(smem + SM_STAT);    // [128][9] padded, j-pair per float2
    float*  s_q = (float*)(smem + SM_Q);           // [128][5] padded
    int*    s_idx = (int*)(smem + SM_IDX);
    const uint32_t sb = smem_u32(smem);

    for (int i = tid; i < K_ * D_; i += 256) s_cb[i] = cb[i];
    if (tid < 128) s_bg2[tid] = g_bg2[tid];

    // ---- load X fp32, split to fp16 hi/lo smem tiles ----
    {
        const int crow = tid >> 1;
        const int cc0 = (tid & 1) << 6;
        int gr = row0 + crow; if (gr >= B) gr = B - 1;
        const float* xs = X + (long)gr * D_ + cc0;
        __half* x1 = sX1 + crow * XS + cc0;
        __half* x2 = sX2 + crow * XS + cc0;
        #pragma unroll
        for (int j = 0; j < 64; j += 4) {
            float4 v = *(const float4*)(xs + j);
            uint32_t h[2], l[2];
            split2(v.x, v.y, h[0], l[0]);
            split2(v.z, v.w, h[1], l[1]);
            *(uint2*)(x1 + j) = *(uint2*)h;
            *(uint2*)(x2 + j) = *(uint2*)l;
        }
    }
    __syncthreads();

    // ---- mma: warp w -> rows (w&3)*32..+31, cols (w>>2)*64..+63, + 1 stats tile ----
    const int mr = (wid & 3) * 32;
    const int wg = wid >> 2;                  // 0 or 1

    float acc[2][8][4];
    float sacc[2][4];
    #pragma unroll
    for (int mt = 0; mt < 2; ++mt) {
        #pragma unroll
        for (int nt = 0; nt < 8; ++nt)
            #pragma unroll
            for (int j = 0; j < 4; ++j) acc[mt][nt][j] = 0.f;
        #pragma unroll
        for (int j = 0; j < 4; ++j) sacc[mt][j] = 0.f;
    }

    const int a_row = lane & 15;
    const int a_koff = (lane >> 4) << 3;
    const uint32_t aB1 = sb + SM_X1 + (uint32_t)(((mr + a_row) * XS + a_koff) * 2);
    const uint32_t aB2 = sb + SM_X2 + (uint32_t)(((mr + a_row) * XS + a_koff) * 2);
    const uint32_t aStep16 = 16 * XS * 2;
    const uint4* __restrict__ bfrag = g_bfrag;

    #pragma unroll 2
    for (int ks = 0; ks < 8; ++ks) {
        const int k0 = ks * 16;
        uint32_t A1[2][4], A2[2][4];
        ldsm_x4(A1[0][0], A1[0][1], A1[0][2], A1[0][3], aB1 + k0 * 2);
        ldsm_x4(A1[1][0], A1[1][1], A1[1][2], A1[1][3], aB1 + aStep16 + k0 * 2);
        ldsm_x4(A2[0][0], A2[0][1], A2[0][2], A2[0][3], aB2 + k0 * 2);
        ldsm_x4(A2[1][0], A2[1][1], A2[1][2], A2[1][3], aB2 + aStep16 + k0 * 2);
        #pragma unroll
        for (int nt = 0; nt < 8; ++nt) {
            uint4 f = __ldg(&bfrag[(ks * NTT + wg * 8 + nt) * 32 + lane]);
            #pragma unroll
            for (int mt = 0; mt < 2; ++mt) {
                mma16816(acc[mt][nt], A1[mt], f.x, f.y);
                mma16816(acc[mt][nt], A1[mt], f.z, f.w);
                mma16816(acc[mt][nt], A2[mt], f.x, f.y);
            }
        }
        {
            uint4 f = __ldg(&bfrag[(ks * NTT + 16 + wg) * 32 + lane]);
            #pragma unroll
            for (int mt = 0; mt < 2; ++mt) {
                mma16816(sacc[mt], A1[mt], f.x, f.y);
                mma16816(sacc[mt], A1[mt], f.z, f.w);
                mma16816(sacc[mt], A2[mt], f.x, f.y);
            }
        }
    }

    // ---- quadratic sums (s2=Sum h^2, s3=Sum h^2 g^2) in fragment domain ----
    const int g4 = lane >> 2, t4 = lane & 3;
    float s2[4] = {0,0,0,0}, s3[4] = {0,0,0,0};    // [mt*2+rh]
    #pragma unroll
    for (int nt = 0; nt < 8; ++nt) {
        const int c0 = wg * 64 + nt * 8 + t4 * 2;
        float2 bgA = s_bg2[c0], bgB = s_bg2[c0 + 1];
        #pragma unroll
        for (int mt = 0; mt < 2; ++mt)
            #pragma unroll
            for (int rh = 0; rh < 2; ++rh) {
                float hA = acc[mt][nt][rh * 2]     + bgA.x;
                float hB = acc[mt][nt][rh * 2 + 1] + bgB.x;
                s2[mt * 2 + rh] = fmaf(hA, hA, s2[mt * 2 + rh]);
                s2[mt * 2 + rh] = fmaf(hB, hB, s2[mt * 2 + rh]);
                s3[mt * 2 + rh] = fmaf(hA * bgA.y, hA, s3[mt * 2 + rh]);
                s3[mt * 2 + rh] = fmaf(hB * bgB.y, hB, s3[mt * 2 + rh]);
            }
    }
    #pragma unroll
    for (int i = 0; i < 4; ++i) { s2[i] = red4(s2[i]); s3[i] = red4(s3[i]); }

    // write partials: quad (lane t4==0) and stats (every lane)
    #pragma unroll
    for (int mt = 0; mt < 2; ++mt)
        #pragma unroll
        for (int rh = 0; rh < 2; ++rh) {
            const int row = mr + mt * 16 + rh * 8 + g4;
            if (t4 == 0) {
                s_q[row * 5 + wg * 2]     = s2[mt * 2 + rh];
                s_q[row * 5 + wg * 2 + 1] = s3[mt * 2 + rh];
            }
            s_stat[row * 9 + wg * 4 + t4] =
                make_float2(sacc[mt][rh * 2], sacc[mt][rh * 2 + 1]);
        }
    __syncthreads();

    // ---- finisher: one thread per row ----
    const long Bl = (long)B;
    const long off_soft = Bl;
    const long off_emb  = Bl + Bl * K_;
    const long off_log  = Bl + Bl * K_ + Bl * D_;

    if (tid < 128) {
        const int row = tid;
        const int r = row0 + row;
        float st[16];
        #pragma unroll
        for (int i = 0; i < 8; ++i) {
            float2 v = s_stat[row * 9 + i];
            st[i * 2] = v.x; st[i * 2 + 1] = v.y;
        }
        const float s2t = s_q[row * 5 + 0] + s_q[row * 5 + 2];
        const float s3t = s_q[row * 5 + 1] + s_q[row * 5 + 3];
        const float s1t = st[0] + __ldg(g_sc2 + 0);
        const float s4t = st[1] + __ldg(g_sc2 + 1);
        const float s5t = st[2] + __ldg(g_sc2 + 2);
        const float Sg2  = __ldg(g_sc2 + 11);
        const float Sgbt = __ldg(g_sc2 + 12);
        const float Sbt2 = __ldg(g_sc2 + 13);

        const float mu = s1t * (1.f / 128.f);
        const float var = s2t * (1.f / 128.f) - mu * mu;
        const float rstd = rsqrtf(var + 1e-5f);
        const float nn = rstd * rstd * (s3t - 2.f * mu * s4t + mu * mu * Sg2)
                       + 2.f * rstd * (s5t - mu * Sgbt) + Sbt2;
        const float rinv = 1.f / fmaxf(sqrtf(nn), 1e-12f);

        float lg[8];
        #pragma unroll
        for (int k = 0; k < 8; ++k) {
            float Sk = st[3 + k] + __ldg(g_sc2 + 3 + k);
            lg[k] = (rstd * (Sk - mu * __ldg(g_sc2 + 14 + k)) + __ldg(g_sc2 + 22 + k)) * rinv;
        }

        float mx = lg[0]; int idx = 0;
        #pragma unroll
        for (int k = 1; k < 8; ++k) if (lg[k] > mx) { mx = lg[k]; idx = k; }
        float e[8]; float se = 0.f;
        #pragma unroll
        for (int k = 0; k < 8; ++k) { e[k] = expf(lg[k] - mx); se += e[k]; }
        const float rse = 1.f / se;

        s_idx[row] = idx;
        if (r < B) {
            if (r < out_size) out[r] = (float)idx;
            long sbo = off_soft + (long)r * K_;
            if (sbo + 7 < out_size) {
                *(float4*)(out + sbo)     = make_float4(e[0]*rse, e[1]*rse, e[2]*rse, e[3]*rse);
                *(float4*)(out + sbo + 4) = make_float4(e[4]*rse, e[5]*rse, e[6]*rse, e[7]*rse);
            }
            long lb = off_log + (long)r * K_;
            if (lb + 7 < out_size) {
                *(float4*)(out + lb)     = make_float4(lg[0], lg[1], lg[2], lg[3]);
                *(float4*)(out + lb + 4) = make_float4(lg[4], lg[5], lg[6], lg[7]);
            }
        }
    }
    __syncthreads();

    // ---- embedding: coalesced gather of codebook[idx] ----
    for (int i = tid; i < 128 * 32; i += 256) {
        int row = i >> 5, c4 = i & 31;
        int r = row0 + row;
        if (r < B) {
            long eb = off_emb + (long)r * D_ + c4 * 4;
            if (eb + 3 < out_size) {
                float4 v = ((float4*)(s_cb + s_idx[row] * D_))[c4];
                *(float4*)(out + eb) = v;
            }
        }
    }
}

extern "C" void kernel_launch(void* const* d_in, const int* in_sizes, int n_in,
                              void* d_out, int out_size) {
    const float* X     = (const float*)d_in[0];
    const float* W     = (const float*)d_in[1];
    const float* bias  = (const float*)d_in[2];
    const float* gamma = (const float*)d_in[3];
    const float* beta  = (const float*)d_in[4];
    const float* cb    = (const float*)d_in[5];
    float* out = (float*)d_out;

    const int B = in_sizes[0] / D_;
    const int grid = (B + 127) / 128;
    l1q_prep<<<17, 256>>>(W, cb, bias, gamma, beta);
    cudaFuncSetAttribute(l1q_mma, cudaFuncAttributeMaxDynamicSharedMemorySize, SMEM_TOTAL);
    l1q_mma<<<grid, 256, SMEM_TOTAL>>>(X, cb, out, B, (long)out_size);
}

// round 9
// speedup vs baseline: 1.1102x; 1.1102x over previous
#include <cuda_runtime.h>
#include <cuda_fp16.h>
#include <stdint.h>
#include <math.h>

#define D_ 128
#define K_ 8
#define XS 136                 // fp16 X tile stride (halves)
#define NTT 18                 // n-tiles in bfrag table: 16 data + 2 stats

// ---- main-kernel dynamic smem layout (bytes) ----
#define SM_X1    0             // 128 x XS halves = 34816
#define SM_X2    34816         // -> 69632
#define SM_CB    69632         // float[8][128] raw codebook -> 73728
#define SM_BG2   73728         // float2[128] {bias, gamma^2} -> 74752
#define SM_STAT  74752         // float2[128][9] padded stats -> 83968
#define SM_Q     83968         // float[128][5] padded quad partials -> 86528
#define SM_IDX   86528         // int[128] -> 87040
#define SMEM_TOTAL 87040

// W + stats pre-split fp16 hi/lo in m16n8k16 B-fragment order:
// g_bfrag[(ks*NTT + gnt)*32 + lane] = {B1hi_r0, B1hi_r1, B1lo_r0, B1lo_r1}
__device__ uint4 g_bfrag[8 * NTT * 32];
__device__ float2 g_bg2[128];     // {bias[c], gamma[c]^2}
// consts: [0..10]=C[j]=Sum bias*v_j, [11]=Sum g^2, [12]=Sum g*bt, [13]=Sum bt^2,
//         [14+k]=e[k]=Sum g*cbn[k], [22+k]=d[k]=Sum bt*cbn[k]
__device__ float g_sc2[30];

__device__ __forceinline__ uint32_t smem_u32(const void* p) {
    uint32_t a;
    asm("{ .reg .u64 t; cvta.to.shared.u64 t, %1; cvt.u32.u64 %0, t; }" : "=r"(a) : "l"(p));
    return a;
}
__device__ __forceinline__ void ldsm_x4(uint32_t& r0, uint32_t& r1, uint32_t& r2, uint32_t& r3,
                                        uint32_t addr) {
    asm volatile("ldmatrix.sync.aligned.m8n8.x4.shared.b16 {%0,%1,%2,%3}, [%4];"
                 : "=r"(r0), "=r"(r1), "=r"(r2), "=r"(r3) : "r"(addr));
}
__device__ __forceinline__ void mma16816(float* c, const uint32_t* a, uint32_t b0, uint32_t b1) {
    asm volatile(
        "mma.sync.aligned.m16n8k16.row.col.f32.f16.f16.f32 "
        "{%0,%1,%2,%3}, {%4,%5,%6,%7}, {%8,%9}, {%0,%1,%2,%3};"
        : "+f"(c[0]), "+f"(c[1]), "+f"(c[2]), "+f"(c[3])
        : "r"(a[0]), "r"(a[1]), "r"(a[2]), "r"(a[3]), "r"(b0), "r"(b1));
}
__device__ __forceinline__ void split2(float x, float y, uint32_t& hi, uint32_t& lo) {
    __half hx = __float2half_rn(x), hy = __float2half_rn(y);
    __half lx = __float2half_rn(x - __half2float(hx));
    __half ly = __float2half_rn(y - __half2float(hy));
    __half2 h2 = __halves2half2(hx, hy), l2 = __halves2half2(lx, ly);
    hi = *(uint32_t*)&h2; lo = *(uint32_t*)&l2;
}
__device__ __forceinline__ float red4(float v) {
    v += __shfl_xor_sync(0xffffffffu, v, 1);
    v += __shfl_xor_sync(0xffffffffu, v, 2);
    return v;
}

// ---- prep: 29 blocks, all independent ----
// blocks 0-15 : W fragments
// blocks 16-26: stats vector j = bid-16 -> V[j][*] + its fragment lanes (+ g_bg2 from j=0)
// block 27    : zero unused stats lanes (j = 11..15)
// block 28    : 30 scalar constants
__global__ void l1q_prep(const float* __restrict__ W, const float* __restrict__ cb,
                         const float* __restrict__ bias, const float* __restrict__ gamma,
                         const float* __restrict__ beta) {
    const int tid = threadIdx.x;
    const int bid = blockIdx.x;

    if (bid < 16) {
        const int t = bid * 256 + tid;                  // 0..4095
        const int lane = t & 31;
        const int gnt = (t >> 5) & 15;
        const int ks = t >> 9;
        const int n = gnt * 8 + (lane >> 2);
        const int k0 = ks * 16 + ((lane & 3) << 1);
        const float* wr = W + n * 128;
        uint4 f;
        split2(wr[k0],     wr[k0 + 1], f.x, f.z);
        split2(wr[k0 + 8], wr[k0 + 9], f.y, f.w);
        g_bfrag[(ks * NTT + gnt) * 32 + lane] = f;
        return;
    }

    if (bid < 27) {
        // stats vector j: v0=1, v1=g^2, v2=g*bt, v_{3+kk}=g*cbn[kk]
        const int j = bid - 16;
        __shared__ float v[128];
        __shared__ float sV[128];
        __shared__ float sred[128];
        __shared__ float sinv;

        if (tid < 128) {
            float g = gamma[tid], bt = beta[tid];
            if (j == 0) {
                v[tid] = 1.f;
                g_bg2[tid] = make_float2(bias[tid], g * g);
            } else if (j == 1) {
                v[tid] = g * g;
            } else if (j == 2) {
                v[tid] = g * bt;
            } else {
                float cv = cb[(j - 3) * 128 + tid];
                sred[tid] = cv * cv;
                __syncthreads();
                if (tid == 0) {
                    float s = 0.f;
                    #pragma unroll 16
                    for (int i = 0; i < 128; ++i) s += sred[i];
                    sinv = 1.f / fmaxf(sqrtf(s), 1e-12f);
                }
                __syncthreads();
                v[tid] = g * cv * sinv;
            }
        }
        __syncthreads();

        if (tid < 128) {
            const int k = tid;
            float a0 = 0, a1 = 0, a2 = 0, a3 = 0;
            #pragma unroll 4
            for (int c = 0; c < 128; c += 4) {
                a0 = fmaf(v[c],     W[c * 128 + k],        a0);
                a1 = fmaf(v[c + 1], W[(c + 1) * 128 + k],  a1);
                a2 = fmaf(v[c + 2], W[(c + 2) * 128 + k],  a2);
                a3 = fmaf(v[c + 3], W[(c + 3) * 128 + k],  a3);
            }
            sV[k] = (a0 + a1) + (a2 + a3);
        }
        __syncthreads();

        if (tid < 32) {
            const int ks = tid >> 2, t4 = tid & 3;
            const int lane = ((j & 7) << 2) | t4;
            const int k0 = ks * 16 + t4 * 2;
            uint4 f;
            split2(sV[k0],     sV[k0 + 1], f.x, f.z);
            split2(sV[k0 + 8], sV[k0 + 9], f.y, f.w);
            g_bfrag[(ks * NTT + 16 + (j >> 3)) * 32 + lane] = f;
        }
        return;
    }

    if (bid == 27) {
        // zero stats lanes for j = 11..15 (g16=1, lane>>2 >= 3)
        for (int e = tid; e < 8 * 20; e += 256) {
            const int ks = e / 20;
            const int lane = 12 + (e % 20);
            g_bfrag[(ks * NTT + 17) * 32 + lane] = make_uint4(0, 0, 0, 0);
        }
        return;
    }

    // bid == 28: scalar constants
    {
        __shared__ float inv[K_];
        const int wid = tid >> 5, lane = tid & 31;
        if (wid < K_) {
            float s = 0.f;
            #pragma unroll
            for (int i = 0; i < 4; ++i) {
                float cv = cb[wid * 128 + lane + 32 * i];
                s = fmaf(cv, cv, s);
            }
            #pragma unroll
            for (int d = 16; d > 0; d >>= 1) s += __shfl_xor_sync(0xffffffffu, s, d);
            if (lane == 0) inv[wid] = 1.f / fmaxf(sqrtf(s), 1e-12f);
        }
        __syncthreads();
        if (tid < 128) {
            const int j = tid >> 2;          // 0..31 (only j<30 written)
            const int q = tid & 3;
            float s = 0.f;
            for (int c = q * 32; c < q * 32 + 32; ++c) {
                float g = gamma[c], bt = beta[c], bs = bias[c];
                float val;
                if (j == 0)       val = bs;
                else if (j == 1)  val = bs * g * g;
                else if (j == 2)  val = bs * g * bt;
                else if (j < 11)  val = bs * g * cb[(j - 3) * 128 + c] * inv[j - 3];
                else if (j == 11) val = g * g;
                else if (j == 12) val = g * bt;
                else if (j == 13) val = bt * bt;
                else if (j < 22)  val = g * cb[(j - 14) * 128 + c] * inv[j - 14];
                else if (j < 30)  val = bt * cb[(j - 22) * 128 + c] * inv[j - 22];
                else              val = 0.f;
                s += val;
            }
            s = red4(s);
            if (q == 0 && j < 30) g_sc2[j] = s;
        }
    }
}

__global__ __launch_bounds__(256, 2) void l1q_mma(
    const float* __restrict__ X, const float* __restrict__ cb,
    float* __restrict__ out, int B, long out_size)
{
    extern __shared__ char smem[];
    const int tid = threadIdx.x;
    const int wid = tid >> 5;
    const int lane = tid & 31;
    const int row0 = blockIdx.x * 128;

    __half* sX1 = (__half*)(smem + SM_X1);
    __half* sX2 = (__half*)(smem + SM_X2);
    float*  s_cb = (float*)(smem + SM_CB);
    float2* s_bg2 = (float2*)(smem + SM_BG2);
    float2* s_stat = (float2*)(smem + SM_STAT);    // [128][9] padded
    float*  s_q = (float*)(smem + SM_Q);           // [128][5] padded
    int*    s_idx = (int*)(smem + SM_IDX);
    const uint32_t sb = smem_u32(smem);

    for (int i = tid; i < K_ * D_; i += 256) s_cb[i] = cb[i];
    if (tid < 128) s_bg2[tid] = g_bg2[tid];

    // ---- load X fp32, split to fp16 hi/lo smem tiles ----
    {
        const int crow = tid >> 1;
        const int cc0 = (tid & 1) << 6;
        int gr = row0 + crow; if (gr >= B) gr = B - 1;
        const float* xs = X + (long)gr * D_ + cc0;
        __half* x1 = sX1 + crow * XS + cc0;
        __half* x2 = sX2 + crow * XS + cc0;
        #pragma unroll
        for (int j = 0; j < 64; j += 4) {
            float4 v = *(const float4*)(xs + j);
            uint32_t h[2], l[2];
            split2(v.x, v.y, h[0], l[0]);
            split2(v.z, v.w, h[1], l[1]);
            *(uint2*)(x1 + j) = *(uint2*)h;
            *(uint2*)(x2 + j) = *(uint2*)l;
        }
    }
    __syncthreads();

    // ---- mma: warp w -> rows (w&3)*32..+31, cols (w>>2)*64..+63, + 1 stats tile ----
    const int mr = (wid & 3) * 32;
    const int wg = wid >> 2;                  // 0 or 1

    float acc[2][8][4];
    float sacc[2][4];
    #pragma unroll
    for (int mt = 0; mt < 2; ++mt) {
        #pragma unroll
        for (int nt = 0; nt < 8; ++nt)
            #pragma unroll
            for (int j = 0; j < 4; ++j) acc[mt][nt][j] = 0.f;
        #pragma unroll
        for (int j = 0; j < 4; ++j) sacc[mt][j] = 0.f;
    }

    const int a_row = lane & 15;
    const int a_koff = (lane >> 4) << 3;
    const uint32_t aB1 = sb + SM_X1 + (uint32_t)(((mr + a_row) * XS + a_koff) * 2);
    const uint32_t aB2 = sb + SM_X2 + (uint32_t)(((mr + a_row) * XS + a_koff) * 2);
    const uint32_t aStep16 = 16 * XS * 2;

    const uint4* __restrict__ bp = g_bfrag + (wg * 8) * 32 + lane;
    const uint4* __restrict__ sp = g_bfrag + (16 + wg) * 32 + lane;

    #pragma unroll 2
    for (int ks = 0; ks < 8; ++ks) {
        const int k0 = ks * 16;
        uint32_t A1[2][4], A2[2][4];
        ldsm_x4(A1[0][0], A1[0][1], A1[0][2], A1[0][3], aB1 + k0 * 2);
        ldsm_x4(A1[1][0], A1[1][1], A1[1][2], A1[1][3], aB1 + aStep16 + k0 * 2);
        ldsm_x4(A2[0][0], A2[0][1], A2[0][2], A2[0][3], aB2 + k0 * 2);
        ldsm_x4(A2[1][0], A2[1][1], A2[1][2], A2[1][3], aB2 + aStep16 + k0 * 2);
        #pragma unroll
        for (int nt = 0; nt < 8; ++nt) {
            uint4 f = __ldg(bp + nt * 32);
            #pragma unroll
            for (int mt = 0; mt < 2; ++mt) {
                mma16816(acc[mt][nt], A1[mt], f.x, f.y);
                mma16816(acc[mt][nt], A1[mt], f.z, f.w);
                mma16816(acc[mt][nt], A2[mt], f.x, f.y);
            }
        }
        {
            uint4 f = __ldg(sp);
            #pragma unroll
            for (int mt = 0; mt < 2; ++mt) {
                mma16816(sacc[mt], A1[mt], f.x, f.y);
                mma16816(sacc[mt], A1[mt], f.z, f.w);
                mma16816(sacc[mt], A2[mt], f.x, f.y);
            }
        }
        bp += NTT * 32;
        sp += NTT * 32;
    }

    // ---- quadratic sums (s2=Sum h^2, s3=Sum h^2 g^2) in fragment domain ----
    const int g4 = lane >> 2, t4 = lane & 3;
    float s2[4] = {0,0,0,0}, s3[4] = {0,0,0,0};    // [mt*2+rh]
    #pragma unroll
    for (int nt = 0; nt < 8; ++nt) {
        const int c0 = wg * 64 + nt * 8 + t4 * 2;
        float2 bgA = s_bg2[c0], bgB = s_bg2[c0 + 1];
        #pragma unroll
        for (int mt = 0; mt < 2; ++mt)
            #pragma unroll
            for (int rh = 0; rh < 2; ++rh) {
                float hA = acc[mt][nt][rh * 2]     + bgA.x;
                float hB = acc[mt][nt][rh * 2 + 1] + bgB.x;
                s2[mt * 2 + rh] = fmaf(hA, hA, s2[mt * 2 + rh]);
                s2[mt * 2 + rh] = fmaf(hB, hB, s2[mt * 2 + rh]);
                s3[mt * 2 + rh] = fmaf(hA * bgA.y, hA, s3[mt * 2 + rh]);
                s3[mt * 2 + rh] = fmaf(hB * bgB.y, hB, s3[mt * 2 + rh]);
            }
    }
    #pragma unroll
    for (int i = 0; i < 4; ++i) { s2[i] = red4(s2[i]); s3[i] = red4(s3[i]); }

    // write partials: quad (lane t4==0) and stats (every lane)
    #pragma unroll
    for (int mt = 0; mt < 2; ++mt)
        #pragma unroll
        for (int rh = 0; rh < 2; ++rh) {
            const int row = mr + mt * 16 + rh * 8 + g4;
            if (t4 == 0) {
                s_q[row * 5 + wg * 2]     = s2[mt * 2 + rh];
                s_q[row * 5 + wg * 2 + 1] = s3[mt * 2 + rh];
            }
            s_stat[row * 9 + wg * 4 + t4] =
                make_float2(sacc[mt][rh * 2], sacc[mt][rh * 2 + 1]);
        }
    __syncthreads();

    // ---- finisher: one thread per row ----
    const long Bl = (long)B;
    const long off_soft = Bl;
    const long off_emb  = Bl + Bl * K_;
    const long off_log  = Bl + Bl * K_ + Bl * D_;

    if (tid < 128) {
        const int row = tid;
        const int r = row0 + row;
        float st[16];
        #pragma unroll
        for (int i = 0; i < 8; ++i) {
            float2 v = s_stat[row * 9 + i];
            st[i * 2] = v.x; st[i * 2 + 1] = v.y;
        }
        const float s2t = s_q[row * 5 + 0] + s_q[row * 5 + 2];
        const float s3t = s_q[row * 5 + 1] + s_q[row * 5 + 3];
        const float s1t = st[0] + __ldg(g_sc2 + 0);
        const float s4t = st[1] + __ldg(g_sc2 + 1);
        const float s5t = st[2] + __ldg(g_sc2 + 2);
        const float Sg2  = __ldg(g_sc2 + 11);
        const float Sgbt = __ldg(g_sc2 + 12);
        const float Sbt2 = __ldg(g_sc2 + 13);

        const float mu = s1t * (1.f / 128.f);
        const float var = s2t * (1.f / 128.f) - mu * mu;
        const float rstd = rsqrtf(var + 1e-5f);
        const float nn = rstd * rstd * (s3t - 2.f * mu * s4t + mu * mu * Sg2)
                       + 2.f * rstd * (s5t - mu * Sgbt) + Sbt2;
        const float rinv = 1.f / fmaxf(sqrtf(nn), 1e-12f);

        float lg[8];
        #pragma unroll
        for (int k = 0; k < 8; ++k) {
            float Sk = st[3 + k] + __ldg(g_sc2 + 3 + k);
            lg[k] = (rstd * (Sk - mu * __ldg(g_sc2 + 14 + k)) + __ldg(g_sc2 + 22 + k)) * rinv;
        }

        float mx = lg[0]; int idx = 0;
        #pragma unroll
        for (int k = 1; k < 8; ++k) if (lg[k] > mx) { mx = lg[k]; idx = k; }
        float e[8]; float se = 0.f;
        #pragma unroll
        for (int k = 0; k < 8; ++k) { e[k] = expf(lg[k] - mx); se += e[k]; }
        const float rse = 1.f / se;

        s_idx[row] = idx;
        if (r < B) {
            if (r < out_size) out[r] = (float)idx;
            long sbo = off_soft + (long)r * K_;
            if (sbo + 7 < out_size) {
                *(float4*)(out + sbo)     = make_float4(e[0]*rse, e[1]*rse, e[2]*rse, e[3]*rse);
                *(float4*)(out + sbo + 4) = make_float4(e[4]*rse, e[5]*rse, e[6]*rse, e[7]*rse);
            }
            long lb = off_log + (long)r * K_;
            if (lb + 7 < out_size) {
                *(float4*)(out + lb)     = make_float4(lg[0], lg[1], lg[2], lg[3]);
                *(float4*)(out + lb + 4) = make_float4(lg[4], lg[5], lg[6], lg[7]);
            }
        }
    }
    __syncthreads();

    // ---- embedding: coalesced gather of codebook[idx] ----
    for (int i = tid; i < 128 * 32; i += 256) {
        int row = i >> 5, c4 = i & 31;
        int r = row0 + row;
        if (r < B) {
            long eb = off_emb + (long)r * D_ + c4 * 4;
            if (eb + 3 < out_size) {
                float4 v = ((float4*)(s_cb + s_idx[row] * D_))[c4];
                *(float4*)(out + eb) = v;
            }
        }
    }
}

extern "C" void kernel_launch(void* const* d_in, const int* in_sizes, int n_in,
                              void* d_out, int out_size) {
    const float* X     = (const float*)d_in[0];
    const float* W     = (const float*)d_in[1];
    const float* bias  = (const float*)d_in[2];
    const float* gamma = (const float*)d_in[3];
    const float* beta  = (const float*)d_in[4];
    const float* cb    = (const float*)d_in[5];
    float* out = (float*)d_out;

    const int B = in_sizes[0] / D_;
    const int grid = (B + 127) / 128;
    l1q_prep<<<29, 256>>>(W, cb, bias, gamma, beta);
    cudaFuncSetAttribute(l1q_mma, cudaFuncAttributeMaxDynamicSharedMemorySize, SMEM_TOTAL);
    l1q_mma<<<grid, 256, SMEM_TOTAL>>>(X, cb, out, B, (long)out_size);
}

// round 10
// speedup vs baseline: 1.2413x; 1.1181x over previous
#include <cuda_runtime.h>
#include <cuda_fp16.h>
#include <stdint.h>
#include <math.h>

#define D_ 128
#define K_ 8
#define NTT 18                 // n-tiles in bfrag table: 16 data + 2 stats

// ---- main-kernel dynamic smem layout (bytes) ----
#define SM_CB    0             // float[8][128] raw codebook -> 4096
#define SM_BG2   4096          // float2[128] {bias, gamma^2} -> 5120
#define SM_STAT  5120          // float2[128][9] padded stats -> 14336
#define SM_Q     14336         // float[128][5] padded quad partials -> 16896
#define SM_IDX   16896         // int[128] -> 17408
#define SMEM_TOTAL 17408

// W + stats pre-split fp16 hi/lo in m16n8k16 B-fragment order:
// g_bfrag[(ks*NTT + gnt)*32 + lane] = {B1hi_r0, B1hi_r1, B1lo_r0, B1lo_r1}
__device__ uint4 g_bfrag[8 * NTT * 32];
__device__ float2 g_bg2[128];     // {bias[c], gamma[c]^2}
// consts: [0..10]=C[j]=Sum bias*v_j, [11]=Sum g^2, [12]=Sum g*bt, [13]=Sum bt^2,
//         [14+k]=e[k]=Sum g*cbn[k], [22+k]=d[k]=Sum bt*cbn[k]
__device__ float g_sc2[30];

__device__ __forceinline__ void mma16816(float* c, const uint32_t* a, uint32_t b0, uint32_t b1) {
    asm volatile(
        "mma.sync.aligned.m16n8k16.row.col.f32.f16.f16.f32 "
        "{%0,%1,%2,%3}, {%4,%5,%6,%7}, {%8,%9}, {%0,%1,%2,%3};"
        : "+f"(c[0]), "+f"(c[1]), "+f"(c[2]), "+f"(c[3])
        : "r"(a[0]), "r"(a[1]), "r"(a[2]), "r"(a[3]), "r"(b0), "r"(b1));
}
__device__ __forceinline__ void split2(float x, float y, uint32_t& hi, uint32_t& lo) {
    __half hx = __float2half_rn(x), hy = __float2half_rn(y);
    __half lx = __float2half_rn(x - __half2float(hx));
    __half ly = __float2half_rn(y - __half2float(hy));
    __half2 h2 = __halves2half2(hx, hy), l2 = __halves2half2(lx, ly);
    hi = *(uint32_t*)&h2; lo = *(uint32_t*)&l2;
}
__device__ __forceinline__ float red4(float v) {
    v += __shfl_xor_sync(0xffffffffu, v, 1);
    v += __shfl_xor_sync(0xffffffffu, v, 2);
    return v;
}

// ---- prep: 29 blocks, all independent (unchanged from round 9) ----
__global__ void l1q_prep(const float* __restrict__ W, const float* __restrict__ cb,
                         const float* __restrict__ bias, const float* __restrict__ gamma,
                         const float* __restrict__ beta) {
    const int tid = threadIdx.x;
    const int bid = blockIdx.x;

    if (bid < 16) {
        const int t = bid * 256 + tid;
        const int lane = t & 31;
        const int gnt = (t >> 5) & 15;
        const int ks = t >> 9;
        const int n = gnt * 8 + (lane >> 2);
        const int k0 = ks * 16 + ((lane & 3) << 1);
        const float* wr = W + n * 128;
        uint4 f;
        split2(wr[k0],     wr[k0 + 1], f.x, f.z);
        split2(wr[k0 + 8], wr[k0 + 9], f.y, f.w);
        g_bfrag[(ks * NTT + gnt) * 32 + lane] = f;
        return;
    }

    if (bid < 27) {
        const int j = bid - 16;
        __shared__ float v[128];
        __shared__ float sV[128];
        __shared__ float sred[128];
        __shared__ float sinv;

        if (tid < 128) {
            float g = gamma[tid], bt = beta[tid];
            if (j == 0) {
                v[tid] = 1.f;
                g_bg2[tid] = make_float2(bias[tid], g * g);
            } else if (j == 1) {
                v[tid] = g * g;
            } else if (j == 2) {
                v[tid] = g * bt;
            } else {
                float cv = cb[(j - 3) * 128 + tid];
                sred[tid] = cv * cv;
                __syncthreads();
                if (tid == 0) {
                    float s = 0.f;
                    #pragma unroll 16
                    for (int i = 0; i < 128; ++i) s += sred[i];
                    sinv = 1.f / fmaxf(sqrtf(s), 1e-12f);
                }
                __syncthreads();
                v[tid] = g * cv * sinv;
            }
        }
        __syncthreads();

        if (tid < 128) {
            const int k = tid;
            float a0 = 0, a1 = 0, a2 = 0, a3 = 0;
            #pragma unroll 4
            for (int c = 0; c < 128; c += 4) {
                a0 = fmaf(v[c],     W[c * 128 + k],        a0);
                a1 = fmaf(v[c + 1], W[(c + 1) * 128 + k],  a1);
                a2 = fmaf(v[c + 2], W[(c + 2) * 128 + k],  a2);
                a3 = fmaf(v[c + 3], W[(c + 3) * 128 + k],  a3);
            }
            sV[k] = (a0 + a1) + (a2 + a3);
        }
        __syncthreads();

        if (tid < 32) {
            const int ks = tid >> 2, t4 = tid & 3;
            const int lane = ((j & 7) << 2) | t4;
            const int k0 = ks * 16 + t4 * 2;
            uint4 f;
            split2(sV[k0],     sV[k0 + 1], f.x, f.z);
            split2(sV[k0 + 8], sV[k0 + 9], f.y, f.w);
            g_bfrag[(ks * NTT + 16 + (j >> 3)) * 32 + lane] = f;
        }
        return;
    }

    if (bid == 27) {
        for (int e = tid; e < 8 * 20; e += 256) {
            const int ks = e / 20;
            const int lane = 12 + (e % 20);
            g_bfrag[(ks * NTT + 17) * 32 + lane] = make_uint4(0, 0, 0, 0);
        }
        return;
    }

    {
        __shared__ float inv[K_];
        const int wid = tid >> 5, lane = tid & 31;
        if (wid < K_) {
            float s = 0.f;
            #pragma unroll
            for (int i = 0; i < 4; ++i) {
                float cv = cb[wid * 128 + lane + 32 * i];
                s = fmaf(cv, cv, s);
            }
            #pragma unroll
            for (int d = 16; d > 0; d >>= 1) s += __shfl_xor_sync(0xffffffffu, s, d);
            if (lane == 0) inv[wid] = 1.f / fmaxf(sqrtf(s), 1e-12f);
        }
        __syncthreads();
        if (tid < 128) {
            const int j = tid >> 2;
            const int q = tid & 3;
            float s = 0.f;
            for (int c = q * 32; c < q * 32 + 32; ++c) {
                float g = gamma[c], bt = beta[c], bs = bias[c];
                float val;
                if (j == 0)       val = bs;
                else if (j == 1)  val = bs * g * g;
                else if (j == 2)  val = bs * g * bt;
                else if (j < 11)  val = bs * g * cb[(j - 3) * 128 + c] * inv[j - 3];
                else if (j == 11) val = g * g;
                else if (j == 12) val = g * bt;
                else if (j == 13) val = bt * bt;
                else if (j < 22)  val = g * cb[(j - 14) * 128 + c] * inv[j - 14];
                else if (j < 30)  val = bt * cb[(j - 22) * 128 + c] * inv[j - 22];
                else              val = 0.f;
                s += val;
            }
            s = red4(s);
            if (q == 0 && j < 30) g_sc2[j] = s;
        }
    }
}

__global__ __launch_bounds__(256, 2) void l1q_mma(
    const float* __restrict__ X, const float* __restrict__ cb,
    float* __restrict__ out, int B, long out_size)
{
    extern __shared__ char smem[];
    const int tid = threadIdx.x;
    const int wid = tid >> 5;
    const int lane = tid & 31;
    const int row0 = blockIdx.x * 128;

    float*  s_cb = (float*)(smem + SM_CB);
    float2* s_bg2 = (float2*)(smem + SM_BG2);
    float2* s_stat = (float2*)(smem + SM_STAT);    // [128][9] padded
    float*  s_q = (float*)(smem + SM_Q);           // [128][5] padded
    int*    s_idx = (int*)(smem + SM_IDX);

    for (int i = tid; i < K_ * D_; i += 256) s_cb[i] = cb[i];
    if (tid < 128) s_bg2[tid] = g_bg2[tid];
    // no __syncthreads needed until after mainloop (smem not read before then)

    // ---- mma: warp w -> rows (w&3)*32..+31, cols (w>>2)*64..+63, + 1 stats tile ----
    const int mr = (wid & 3) * 32;
    const int wg = wid >> 2;                  // 0 or 1
    const int g4 = lane >> 2, t4 = lane & 3;

    float acc[2][8][4];
    float sacc[2][4];
    #pragma unroll
    for (int mt = 0; mt < 2; ++mt) {
        #pragma unroll
        for (int nt = 0; nt < 8; ++nt)
            #pragma unroll
            for (int j = 0; j < 4; ++j) acc[mt][nt][j] = 0.f;
        #pragma unroll
        for (int j = 0; j < 4; ++j) sacc[mt][j] = 0.f;
    }

    // A-fragment source rows: mr + g4 + {0,8,16,24}, col base t4*2
    const float* pR[4];
    #pragma unroll
    for (int i = 0; i < 4; ++i) {
        int gr = row0 + mr + g4 + i * 8;
        if (gr >= B) gr = B - 1;
        pR[i] = X + (long)gr * D_ + t4 * 2;
    }

    const uint4* __restrict__ bp = g_bfrag + (wg * 8) * 32 + lane;
    const uint4* __restrict__ sp = g_bfrag + (16 + wg) * 32 + lane;

    #pragma unroll 2
    for (int ks = 0; ks < 8; ++ks) {
        const int k0 = ks * 16;
        // load A fragments straight from global (coalesced 32B per 4-lane group)
        float2 xa[4][2];
        #pragma unroll
        for (int i = 0; i < 4; ++i) {
            xa[i][0] = *(const float2*)(pR[i] + k0);
            xa[i][1] = *(const float2*)(pR[i] + k0 + 8);
        }
        uint32_t A1[2][4], A2[2][4];
        #pragma unroll
        for (int mt = 0; mt < 2; ++mt) {
            split2(xa[mt * 2][0].x,     xa[mt * 2][0].y,     A1[mt][0], A2[mt][0]);
            split2(xa[mt * 2 + 1][0].x, xa[mt * 2 + 1][0].y, A1[mt][1], A2[mt][1]);
            split2(xa[mt * 2][1].x,     xa[mt * 2][1].y,     A1[mt][2], A2[mt][2]);
            split2(xa[mt * 2 + 1][1].x, xa[mt * 2 + 1][1].y, A1[mt][3], A2[mt][3]);
        }
        #pragma unroll
        for (int nt = 0; nt < 8; ++nt) {
            uint4 f = __ldg(bp + nt * 32);
            #pragma unroll
            for (int mt = 0; mt < 2; ++mt) {
                mma16816(acc[mt][nt], A1[mt], f.x, f.y);
                mma16816(acc[mt][nt], A1[mt], f.z, f.w);
                mma16816(acc[mt][nt], A2[mt], f.x, f.y);
            }
        }
        {
            uint4 f = __ldg(sp);
            #pragma unroll
            for (int mt = 0; mt < 2; ++mt) {
                mma16816(sacc[mt], A1[mt], f.x, f.y);
                mma16816(sacc[mt], A1[mt], f.z, f.w);
                mma16816(sacc[mt], A2[mt], f.x, f.y);
            }
        }
        bp += NTT * 32;
        sp += NTT * 32;
    }
    __syncthreads();   // staging (s_bg2/s_cb) now guaranteed visible

    // ---- quadratic sums (s2=Sum h^2, s3=Sum h^2 g^2) in fragment domain ----
    float s2[4] = {0,0,0,0}, s3[4] = {0,0,0,0};    // [mt*2+rh]
    #pragma unroll
    for (int nt = 0; nt < 8; ++nt) {
        const int c0 = wg * 64 + nt * 8 + t4 * 2;
        float2 bgA = s_bg2[c0], bgB = s_bg2[c0 + 1];
        #pragma unroll
        for (int mt = 0; mt < 2; ++mt)
            #pragma unroll
            for (int rh = 0; rh < 2; ++rh) {
                float hA = acc[mt][nt][rh * 2]     + bgA.x;
                float hB = acc[mt][nt][rh * 2 + 1] + bgB.x;
                s2[mt * 2 + rh] = fmaf(hA, hA, s2[mt * 2 + rh]);
                s2[mt * 2 + rh] = fmaf(hB, hB, s2[mt * 2 + rh]);
                s3[mt * 2 + rh] = fmaf(hA * bgA.y, hA, s3[mt * 2 + rh]);
                s3[mt * 2 + rh] = fmaf(hB * bgB.y, hB, s3[mt * 2 + rh]);
            }
    }
    #pragma unroll
    for (int i = 0; i < 4; ++i) { s2[i] = red4(s2[i]); s3[i] = red4(s3[i]); }

    #pragma unroll
    for (int mt = 0; mt < 2; ++mt)
        #pragma unroll
        for (int rh = 0; rh < 2; ++rh) {
            const int row = mr + mt * 16 + rh * 8 + g4;
            if (t4 == 0) {
                s_q[row * 5 + wg * 2]     = s2[mt * 2 + rh];
                s_q[row * 5 + wg * 2 + 1] = s3[mt * 2 + rh];
            }
            s_stat[row * 9 + wg * 4 + t4] =
                make_float2(sacc[mt][rh * 2], sacc[mt][rh * 2 + 1]);
        }
    __syncthreads();

    // ---- finisher: one thread per row ----
    const long Bl = (long)B;
    const long off_soft = Bl;
    const long off_emb  = Bl + Bl * K_;
    const long off_log  = Bl + Bl * K_ + Bl * D_;

    if (tid < 128) {
        const int row = tid;
        const int r = row0 + row;
        float st[16];
        #pragma unroll
        for (int i = 0; i < 8; ++i) {
            float2 v = s_stat[row * 9 + i];
            st[i * 2] = v.x; st[i * 2 + 1] = v.y;
        }
        const float s2t = s_q[row * 5 + 0] + s_q[row * 5 + 2];
        const float s3t = s_q[row * 5 + 1] + s_q[row * 5 + 3];
        const float s1t = st[0] + __ldg(g_sc2 + 0);
        const float s4t = st[1] + __ldg(g_sc2 + 1);
        const float s5t = st[2] + __ldg(g_sc2 + 2);
        const float Sg2  = __ldg(g_sc2 + 11);
        const float Sgbt = __ldg(g_sc2 + 12);
        const float Sbt2 = __ldg(g_sc2 + 13);

        const float mu = s1t * (1.f / 128.f);
        const float var = s2t * (1.f / 128.f) - mu * mu;
        const float rstd = rsqrtf(var + 1e-5f);
        const float nn = rstd * rstd * (s3t - 2.f * mu * s4t + mu * mu * Sg2)
                       + 2.f * rstd * (s5t - mu * Sgbt) + Sbt2;
        const float rinv = 1.f / fmaxf(sqrtf(nn), 1e-12f);

        float lg[8];
        #pragma unroll
        for (int k = 0; k < 8; ++k) {
            float Sk = st[3 + k] + __ldg(g_sc2 + 3 + k);
            lg[k] = (rstd * (Sk - mu * __ldg(g_sc2 + 14 + k)) + __ldg(g_sc2 + 22 + k)) * rinv;
        }

        float mx = lg[0]; int idx = 0;
        #pragma unroll
        for (int k = 1; k < 8; ++k) if (lg[k] > mx) { mx = lg[k]; idx = k; }
        float e[8]; float se = 0.f;
        #pragma unroll
        for (int k = 0; k < 8; ++k) { e[k] = expf(lg[k] - mx); se += e[k]; }
        const float rse = 1.f / se;

        s_idx[row] = idx;
        if (r < B) {
            if (r < out_size) out[r] = (float)idx;
            long sbo = off_soft + (long)r * K_;
            if (sbo + 7 < out_size) {
                *(float4*)(out + sbo)     = make_float4(e[0]*rse, e[1]*rse, e[2]*rse, e[3]*rse);
                *(float4*)(out + sbo + 4) = make_float4(e[4]*rse, e[5]*rse, e[6]*rse, e[7]*rse);
            }
            long lb = off_log + (long)r * K_;
            if (lb + 7 < out_size) {
                *(float4*)(out + lb)     = make_float4(lg[0], lg[1], lg[2], lg[3]);
                *(float4*)(out + lb + 4) = make_float4(lg[4], lg[5], lg[6], lg[7]);
            }
        }
    }
    __syncthreads();

    // ---- embedding: coalesced gather of codebook[idx] ----
    for (int i = tid; i < 128 * 32; i += 256) {
        int row = i >> 5, c4 = i & 31;
        int r = row0 + row;
        if (r < B) {
            long eb = off_emb + (long)r * D_ + c4 * 4;
            if (eb + 3 < out_size) {
                float4 v = ((float4*)(s_cb + s_idx[row] * D_))[c4];
                *(float4*)(out + eb) = v;
            }
        }
    }
}

extern "C" void kernel_launch(void* const* d_in, const int* in_sizes, int n_in,
                              void* d_out, int out_size) {
    const float* X     = (const float*)d_in[0];
    const float* W     = (const float*)d_in[1];
    const float* bias  = (const float*)d_in[2];
    const float* gamma = (const float*)d_in[3];
    const float* beta  = (const float*)d_in[4];
    const float* cb    = (const float*)d_in[5];
    float* out = (float*)d_out;

    const int B = in_sizes[0] / D_;
    const int grid = (B + 127) / 128;
    l1q_prep<<<29, 256>>>(W, cb, bias, gamma, beta);
    cudaFuncSetAttribute(l1q_mma, cudaFuncAttributeMaxDynamicSharedMemorySize, SMEM_TOTAL);
    l1q_mma<<<grid, 256, SMEM_TOTAL>>>(X, cb, out, B, (long)out_size);
}

// round 11
// speedup vs baseline: 1.3538x; 1.0907x over previous
#include <cuda_runtime.h>
#include <cuda_fp16.h>
#include <stdint.h>
#include <math.h>

#define D_ 128
#define K_ 8
#define NTT 18                 // n-tiles in bfrag table: 16 data + 2 stats

// ---- main-kernel dynamic smem layout (bytes) ----
#define SM_CB    0             // float[8][128] raw codebook -> 4096
#define SM_BG2   4096          // float2[128] {bias, gamma^2} -> 5120
#define SM_STAT  5120          // float2[128][9] padded stats -> 14336
#define SM_Q     14336         // float[128][5] padded quad partials -> 16896
#define SM_IDX   16896         // int[128] -> 17408
#define SMEM_TOTAL 17408

// W + stats pre-split fp16 hi/lo in m16n8k16 B-fragment order:
// g_bfrag[(ks*NTT + gnt)*32 + lane] = {B1hi_r0, B1hi_r1, B1lo_r0, B1lo_r1}
__device__ uint4 g_bfrag[8 * NTT * 32];
__device__ float2 g_bg2[128];     // {bias[c], gamma[c]^2}
// consts: [0..10]=C[j]=Sum bias*v_j, [11]=Sum g^2, [12]=Sum g*bt, [13]=Sum bt^2,
//         [14+k]=e[k]=Sum g*cbn[k], [22+k]=d[k]=Sum bt*cbn[k]
__device__ float g_sc2[30];

__device__ __forceinline__ void mma16816(float* c, const uint32_t* a, uint32_t b0, uint32_t b1) {
    asm volatile(
        "mma.sync.aligned.m16n8k16.row.col.f32.f16.f16.f32 "
        "{%0,%1,%2,%3}, {%4,%5,%6,%7}, {%8,%9}, {%0,%1,%2,%3};"
        : "+f"(c[0]), "+f"(c[1]), "+f"(c[2]), "+f"(c[3])
        : "r"(a[0]), "r"(a[1]), "r"(a[2]), "r"(a[3]), "r"(b0), "r"(b1));
}
__device__ __forceinline__ void split2(float x, float y, uint32_t& hi, uint32_t& lo) {
    __half hx = __float2half_rn(x), hy = __float2half_rn(y);
    __half lx = __float2half_rn(x - __half2float(hx));
    __half ly = __float2half_rn(y - __half2float(hy));
    __half2 h2 = __halves2half2(hx, hy), l2 = __halves2half2(lx, ly);
    hi = *(uint32_t*)&h2; lo = *(uint32_t*)&l2;
}
// packed variant: 2 floats -> (hi half2, lo half2) via F2FP.PACK
__device__ __forceinline__ void split2v(float2 v, uint32_t& hi, uint32_t& lo) {
    __half2 h = __floats2half2_rn(v.x, v.y);
    float2 hf = __half22float2(h);
    __half2 l = __floats2half2_rn(v.x - hf.x, v.y - hf.y);
    hi = *(uint32_t*)&h; lo = *(uint32_t*)&l;
}
__device__ __forceinline__ float red4(float v) {
    v += __shfl_xor_sync(0xffffffffu, v, 1);
    v += __shfl_xor_sync(0xffffffffu, v, 2);
    return v;
}

// ---- prep: 29 blocks, all independent (unchanged) ----
__global__ void l1q_prep(const float* __restrict__ W, const float* __restrict__ cb,
                         const float* __restrict__ bias, const float* __restrict__ gamma,
                         const float* __restrict__ beta) {
    const int tid = threadIdx.x;
    const int bid = blockIdx.x;

    if (bid < 16) {
        const int t = bid * 256 + tid;
        const int lane = t & 31;
        const int gnt = (t >> 5) & 15;
        const int ks = t >> 9;
        const int n = gnt * 8 + (lane >> 2);
        const int k0 = ks * 16 + ((lane & 3) << 1);
        const float* wr = W + n * 128;
        uint4 f;
        split2(wr[k0],     wr[k0 + 1], f.x, f.z);
        split2(wr[k0 + 8], wr[k0 + 9], f.y, f.w);
        g_bfrag[(ks * NTT + gnt) * 32 + lane] = f;
        return;
    }

    if (bid < 27) {
        const int j = bid - 16;
        __shared__ float v[128];
        __shared__ float sV[128];
        __shared__ float sred[128];
        __shared__ float sinv;

        if (tid < 128) {
            float g = gamma[tid], bt = beta[tid];
            if (j == 0) {
                v[tid] = 1.f;
                g_bg2[tid] = make_float2(bias[tid], g * g);
            } else if (j == 1) {
                v[tid] = g * g;
            } else if (j == 2) {
                v[tid] = g * bt;
            } else {
                float cv = cb[(j - 3) * 128 + tid];
                sred[tid] = cv * cv;
                __syncthreads();
                if (tid == 0) {
                    float s = 0.f;
                    #pragma unroll 16
                    for (int i = 0; i < 128; ++i) s += sred[i];
                    sinv = 1.f / fmaxf(sqrtf(s), 1e-12f);
                }
                __syncthreads();
                v[tid] = g * cv * sinv;
            }
        }
        __syncthreads();

        if (tid < 128) {
            const int k = tid;
            float a0 = 0, a1 = 0, a2 = 0, a3 = 0;
            #pragma unroll 4
            for (int c = 0; c < 128; c += 4) {
                a0 = fmaf(v[c],     W[c * 128 + k],        a0);
                a1 = fmaf(v[c + 1], W[(c + 1) * 128 + k],  a1);
                a2 = fmaf(v[c + 2], W[(c + 2) * 128 + k],  a2);
                a3 = fmaf(v[c + 3], W[(c + 3) * 128 + k],  a3);
            }
            sV[k] = (a0 + a1) + (a2 + a3);
        }
        __syncthreads();

        if (tid < 32) {
            const int ks = tid >> 2, t4 = tid & 3;
            const int lane = ((j & 7) << 2) | t4;
            const int k0 = ks * 16 + t4 * 2;
            uint4 f;
            split2(sV[k0],     sV[k0 + 1], f.x, f.z);
            split2(sV[k0 + 8], sV[k0 + 9], f.y, f.w);
            g_bfrag[(ks * NTT + 16 + (j >> 3)) * 32 + lane] = f;
        }
        return;
    }

    if (bid == 27) {
        for (int e = tid; e < 8 * 20; e += 256) {
            const int ks = e / 20;
            const int lane = 12 + (e % 20);
            g_bfrag[(ks * NTT + 17) * 32 + lane] = make_uint4(0, 0, 0, 0);
        }
        return;
    }

    {
        __shared__ float inv[K_];
        const int wid = tid >> 5, lane = tid & 31;
        if (wid < K_) {
            float s = 0.f;
            #pragma unroll
            for (int i = 0; i < 4; ++i) {
                float cv = cb[wid * 128 + lane + 32 * i];
                s = fmaf(cv, cv, s);
            }
            #pragma unroll
            for (int d = 16; d > 0; d >>= 1) s += __shfl_xor_sync(0xffffffffu, s, d);
            if (lane == 0) inv[wid] = 1.f / fmaxf(sqrtf(s), 1e-12f);
        }
        __syncthreads();
        if (tid < 128) {
            const int j = tid >> 2;
            const int q = tid & 3;
            float s = 0.f;
            for (int c = q * 32; c < q * 32 + 32; ++c) {
                float g = gamma[c], bt = beta[c], bs = bias[c];
                float val;
                if (j == 0)       val = bs;
                else if (j == 1)  val = bs * g * g;
                else if (j == 2)  val = bs * g * bt;
                else if (j < 11)  val = bs * g * cb[(j - 3) * 128 + c] * inv[j - 3];
                else if (j == 11) val = g * g;
                else if (j == 12) val = g * bt;
                else if (j == 13) val = bt * bt;
                else if (j < 22)  val = g * cb[(j - 14) * 128 + c] * inv[j - 14];
                else if (j < 30)  val = bt * cb[(j - 22) * 128 + c] * inv[j - 22];
                else              val = 0.f;
                s += val;
            }
            s = red4(s);
            if (q == 0 && j < 30) g_sc2[j] = s;
        }
    }
}

__global__ __launch_bounds__(256, 2) void l1q_mma(
    const float* __restrict__ X, const float* __restrict__ cb,
    float* __restrict__ out, int B, long out_size)
{
    extern __shared__ char smem[];
    const int tid = threadIdx.x;
    const int wid = tid >> 5;
    const int lane = tid & 31;
    const int row0 = blockIdx.x * 128;

    float*  s_cb = (float*)(smem + SM_CB);
    float2* s_bg2 = (float2*)(smem + SM_BG2);
    float2* s_stat = (float2*)(smem + SM_STAT);    // [128][9] padded
    float*  s_q = (float*)(smem + SM_Q);           // [128][5] padded
    int*    s_idx = (int*)(smem + SM_IDX);

    for (int i = tid; i < K_ * D_; i += 256) s_cb[i] = cb[i];
    if (tid < 128) s_bg2[tid] = g_bg2[tid];

    // ---- mma: warp w -> rows (w&3)*32..+31, cols (w>>2)*64..+63, + 1 stats tile ----
    const int mr = (wid & 3) * 32;
    const int wg = wid >> 2;                  // 0 or 1
    const int g4 = lane >> 2, t4 = lane & 3;

    float acc[2][8][4];
    float sacc[2][4];
    #pragma unroll
    for (int mt = 0; mt < 2; ++mt) {
        #pragma unroll
        for (int nt = 0; nt < 8; ++nt)
            #pragma unroll
            for (int j = 0; j < 4; ++j) acc[mt][nt][j] = 0.f;
        #pragma unroll
        for (int j = 0; j < 4; ++j) sacc[mt][j] = 0.f;
    }

    // A-fragment source rows: mr + g4 + {0,8,16,24}, col base t4*2
    const float* pR[4];
    #pragma unroll
    for (int i = 0; i < 4; ++i) {
        int gr = row0 + mr + g4 + i * 8;
        if (gr >= B) gr = B - 1;
        pR[i] = X + (long)gr * D_ + t4 * 2;
    }

    const uint4* __restrict__ bp = g_bfrag + (wg * 8) * 32 + lane;
    const uint4* __restrict__ sp = g_bfrag + (16 + wg) * 32 + lane;

    // software pipeline: raw X for current ks in registers, next-ks loads issued
    // immediately after conversion (one full mma block of prefetch distance)
    float2 c0[4], c1[4];
    #pragma unroll
    for (int i = 0; i < 4; ++i) {
        c0[i] = *(const float2*)(pR[i]);
        c1[i] = *(const float2*)(pR[i] + 8);
    }

    #pragma unroll
    for (int ks = 0; ks < 8; ++ks) {
        // convert current ks to fragments (packed F2FP)
        uint32_t A1[2][4], A2[2][4];
        #pragma unroll
        for (int mt = 0; mt < 2; ++mt) {
            split2v(c0[mt * 2],     A1[mt][0], A2[mt][0]);
            split2v(c0[mt * 2 + 1], A1[mt][1], A2[mt][1]);
            split2v(c1[mt * 2],     A1[mt][2], A2[mt][2]);
            split2v(c1[mt * 2 + 1], A1[mt][3], A2[mt][3]);
        }
        // prefetch next ks (overlaps the 54-HMMA block below)
        if (ks < 7) {
            const int k1 = (ks + 1) * 16;
            #pragma unroll
            for (int i = 0; i < 4; ++i) {
                c0[i] = *(const float2*)(pR[i] + k1);
                c1[i] = *(const float2*)(pR[i] + k1 + 8);
            }
        }
        #pragma unroll
        for (int nt = 0; nt < 8; ++nt) {
            uint4 f = __ldg(bp + (ks * NTT + nt) * 32);
            #pragma unroll
            for (int mt = 0; mt < 2; ++mt) {
                mma16816(acc[mt][nt], A1[mt], f.x, f.y);
                mma16816(acc[mt][nt], A1[mt], f.z, f.w);
                mma16816(acc[mt][nt], A2[mt], f.x, f.y);
            }
        }
        {
            uint4 f = __ldg(sp + ks * NTT * 32);
            #pragma unroll
            for (int mt = 0; mt < 2; ++mt) {
                mma16816(sacc[mt], A1[mt], f.x, f.y);
                mma16816(sacc[mt], A1[mt], f.z, f.w);
                mma16816(sacc[mt], A2[mt], f.x, f.y);
            }
        }
    }
    __syncthreads();   // staging (s_bg2/s_cb) now guaranteed visible

    // ---- quadratic sums (s2=Sum h^2, s3=Sum h^2 g^2) in fragment domain ----
    float s2[4] = {0,0,0,0}, s3[4] = {0,0,0,0};    // [mt*2+rh]
    #pragma unroll
    for (int nt = 0; nt < 8; ++nt) {
        const int c0i = wg * 64 + nt * 8 + t4 * 2;
        float2 bgA = s_bg2[c0i], bgB = s_bg2[c0i + 1];
        #pragma unroll
        for (int mt = 0; mt < 2; ++mt)
            #pragma unroll
            for (int rh = 0; rh < 2; ++rh) {
                float hA = acc[mt][nt][rh * 2]     + bgA.x;
                float hB = acc[mt][nt][rh * 2 + 1] + bgB.x;
                s2[mt * 2 + rh] = fmaf(hA, hA, s2[mt * 2 + rh]);
                s2[mt * 2 + rh] = fmaf(hB, hB, s2[mt * 2 + rh]);
                s3[mt * 2 + rh] = fmaf(hA * bgA.y, hA, s3[mt * 2 + rh]);
                s3[mt * 2 + rh] = fmaf(hB * bgB.y, hB, s3[mt * 2 + rh]);
            }
    }
    #pragma unroll
    for (int i = 0; i < 4; ++i) { s2[i] = red4(s2[i]); s3[i] = red4(s3[i]); }

    #pragma unroll
    for (int mt = 0; mt < 2; ++mt)
        #pragma unroll
        for (int rh = 0; rh < 2; ++rh) {
            const int row = mr + mt * 16 + rh * 8 + g4;
            if (t4 == 0) {
                s_q[row * 5 + wg * 2]     = s2[mt * 2 + rh];
                s_q[row * 5 + wg * 2 + 1] = s3[mt * 2 + rh];
            }
            s_stat[row * 9 + wg * 4 + t4] =
                make_float2(sacc[mt][rh * 2], sacc[mt][rh * 2 + 1]);
        }
    __syncthreads();

    // ---- finisher: one thread per row ----
    const long Bl = (long)B;
    const long off_soft = Bl;
    const long off_emb  = Bl + Bl * K_;
    const long off_log  = Bl + Bl * K_ + Bl * D_;

    if (tid < 128) {
        const int row = tid;
        const int r = row0 + row;
        float st[16];
        #pragma unroll
        for (int i = 0; i < 8; ++i) {
            float2 v = s_stat[row * 9 + i];
            st[i * 2] = v.x; st[i * 2 + 1] = v.y;
        }
        const float s2t = s_q[row * 5 + 0] + s_q[row * 5 + 2];
        const float s3t = s_q[row * 5 + 1] + s_q[row * 5 + 3];
        const float s1t = st[0] + __ldg(g_sc2 + 0);
        const float s4t = st[1] + __ldg(g_sc2 + 1);
        const float s5t = st[2] + __ldg(g_sc2 + 2);
        const float Sg2  = __ldg(g_sc2 + 11);
        const float Sgbt = __ldg(g_sc2 + 12);
        const float Sbt2 = __ldg(g_sc2 + 13);

        const float mu = s1t * (1.f / 128.f);
        const float var = s2t * (1.f / 128.f) - mu * mu;
        const float rstd = rsqrtf(var + 1e-5f);
        const float nn = rstd * rstd * (s3t - 2.f * mu * s4t + mu * mu * Sg2)
                       + 2.f * rstd * (s5t - mu * Sgbt) + Sbt2;
        const float rinv = 1.f / fmaxf(sqrtf(nn), 1e-12f);

        float lg[8];
        #pragma unroll
        for (int k = 0; k < 8; ++k) {
            float Sk = st[3 + k] + __ldg(g_sc2 + 3 + k);
            lg[k] = (rstd * (Sk - mu * __ldg(g_sc2 + 14 + k)) + __ldg(g_sc2 + 22 + k)) * rinv;
        }

        float mx = lg[0]; int idx = 0;
        #pragma unroll
        for (int k = 1; k < 8; ++k) if (lg[k] > mx) { mx = lg[k]; idx = k; }
        float e[8]; float se = 0.f;
        #pragma unroll
        for (int k = 0; k < 8; ++k) { e[k] = expf(lg[k] - mx); se += e[k]; }
        const float rse = 1.f / se;

        s_idx[row] = idx;
        if (r < B) {
            if (r < out_size) out[r] = (float)idx;
            long sbo = off_soft + (long)r * K_;
            if (sbo + 7 < out_size) {
                *(float4*)(out + sbo)     = make_float4(e[0]*rse, e[1]*rse, e[2]*rse, e[3]*rse);
                *(float4*)(out + sbo + 4) = make_float4(e[4]*rse, e[5]*rse, e[6]*rse, e[7]*rse);
            }
            long lb = off_log + (long)r * K_;
            if (lb + 7 < out_size) {
                *(float4*)(out + lb)     = make_float4(lg[0], lg[1], lg[2], lg[3]);
                *(float4*)(out + lb + 4) = make_float4(lg[4], lg[5], lg[6], lg[7]);
            }
        }
    }
    __syncthreads();

    // ---- embedding: coalesced gather of codebook[idx] ----
    for (int i = tid; i < 128 * 32; i += 256) {
        int row = i >> 5, c4 = i & 31;
        int r = row0 + row;
        if (r < B) {
            long eb = off_emb + (long)r * D_ + c4 * 4;
            if (eb + 3 < out_size) {
                float4 v = ((float4*)(s_cb + s_idx[row] * D_))[c4];
                *(float4*)(out + eb) = v;
            }
        }
    }
}

extern "C" void kernel_launch(void* const* d_in, const int* in_sizes, int n_in,
                              void* d_out, int out_size) {
    const float* X     = (const float*)d_in[0];
    const float* W     = (const float*)d_in[1];
    const float* bias  = (const float*)d_in[2];
    const float* gamma = (const float*)d_in[3];
    const float* beta  = (const float*)d_in[4];
    const float* cb    = (const float*)d_in[5];
    float* out = (float*)d_out;

    const int B = in_sizes[0] / D_;
    const int grid = (B + 127) / 128;
    l1q_prep<<<29, 256>>>(W, cb, bias, gamma, beta);
    cudaFuncSetAttribute(l1q_mma, cudaFuncAttributeMaxDynamicSharedMemorySize, SMEM_TOTAL);
    l1q_mma<<<grid, 256, SMEM_TOTAL>>>(X, cb, out, B, (long)out_size);
}